// round 1
// baseline (speedup 1.0000x reference)
#include <cuda_runtime.h>

#define N_NODES 100000
#define N_EDGES 1600000
#define HID 64
#define NGRAPH 4096
#define BN_EPS 1e-5f

// ---------------- scratch (device globals; no allocations) ----------------
__device__ __align__(16) float g_h[N_NODES * HID];    // linear output h (gather source)
__device__ __align__(16) float g_agg[N_NODES * HID];  // agg / post-relu y (ping)
__device__ float g_deg[N_NODES];
__device__ float g_dinv[N_NODES];
__device__ float g_enorm[N_EDGES];
__device__ float g_stats[2 * HID];                    // [sum(64), sumsq(64)]
__device__ __align__(16) float g_affine[2 * HID];     // [a(64), d(64)]: x' = y*a + d

// ---------------- degree / norm ----------------
__global__ void zero_deg_kernel() {
    int i = blockIdx.x * blockDim.x + threadIdx.x;
    if (i < N_NODES) g_deg[i] = 0.f;
}

__global__ void deg_kernel(const int* __restrict__ dst) {
    int e = blockIdx.x * blockDim.x + threadIdx.x;
    if (e < N_EDGES) atomicAdd(&g_deg[dst[e]], 1.f);
}

__global__ void dinv_kernel() {
    int i = blockIdx.x * blockDim.x + threadIdx.x;
    if (i < N_NODES) g_dinv[i] = rsqrtf(g_deg[i] + 1.f);
}

__global__ void enorm_kernel(const int* __restrict__ src, const int* __restrict__ dst) {
    int e = blockIdx.x * blockDim.x + threadIdx.x;
    if (e < N_EDGES) g_enorm[e] = g_dinv[src[e]] * g_dinv[dst[e]];
}

// ---------------- GEMM: h = X @ W ; agg = h*self_norm + b ----------------
// Block: 256 threads, 64-node tile, each thread computes 4 nodes x 4 cols.
// FROM_AGG: read input from g_agg (previous layer's post-relu y) and apply
// the folded BN affine x' = y*a[k] + d[k].
template <int IN, bool FROM_AGG>
__global__ __launch_bounds__(256) void gemm_kernel(const float* __restrict__ X,
                                                   const float* __restrict__ W,
                                                   const float* __restrict__ bias) {
    __shared__ __align__(16) float Ws[IN * HID];
    __shared__ float Xs[64 * (IN + 1)];
    __shared__ __align__(16) float s_b[HID];
    __shared__ float s_a[HID];
    __shared__ float s_dd[HID];

    int tid = threadIdx.x;

    // zero BN stats for this layer (consumed later in the same stream order)
    if (blockIdx.x == 0 && tid < 2 * HID) g_stats[tid] = 0.f;

    for (int i = tid; i < IN * HID; i += 256) Ws[i] = W[i];
    if (tid < HID) {
        s_b[tid] = bias[tid];
        if (FROM_AGG) {
            s_a[tid]  = g_affine[tid];
            s_dd[tid] = g_affine[HID + tid];
        }
    }
    __syncthreads();

    int base = blockIdx.x * 64;
    for (int i = tid; i < 64 * IN; i += 256) {
        int n = i / IN, k = i - n * IN;
        int gn = base + n;
        float v = 0.f;
        if (gn < N_NODES) {
            if (FROM_AGG) v = g_agg[gn * HID + k] * s_a[k] + s_dd[k];
            else          v = X[gn * IN + k];
        }
        Xs[n * (IN + 1) + k] = v;
    }
    __syncthreads();

    int tx = tid & 15, ty = tid >> 4;
    int c0 = tx * 4, n0 = ty * 4;
    float4 a0 = {0.f, 0.f, 0.f, 0.f};
    float4 a1 = {0.f, 0.f, 0.f, 0.f};
    float4 a2 = {0.f, 0.f, 0.f, 0.f};
    float4 a3 = {0.f, 0.f, 0.f, 0.f};

#pragma unroll 5
    for (int k = 0; k < IN; k++) {
        float4 w = *(const float4*)&Ws[k * HID + c0];
        float x0 = Xs[(n0 + 0) * (IN + 1) + k];
        float x1 = Xs[(n0 + 1) * (IN + 1) + k];
        float x2 = Xs[(n0 + 2) * (IN + 1) + k];
        float x3 = Xs[(n0 + 3) * (IN + 1) + k];
        a0.x += x0 * w.x; a0.y += x0 * w.y; a0.z += x0 * w.z; a0.w += x0 * w.w;
        a1.x += x1 * w.x; a1.y += x1 * w.y; a1.z += x1 * w.z; a1.w += x1 * w.w;
        a2.x += x2 * w.x; a2.y += x2 * w.y; a2.z += x2 * w.z; a2.w += x2 * w.w;
        a3.x += x3 * w.x; a3.y += x3 * w.y; a3.z += x3 * w.z; a3.w += x3 * w.w;
    }

    float4 bb = *(const float4*)&s_b[c0];
    float4 accs[4] = {a0, a1, a2, a3};
#pragma unroll
    for (int i = 0; i < 4; i++) {
        int gn = base + n0 + i;
        if (gn >= N_NODES) break;
        float dv = g_dinv[gn];
        float sn = dv * dv;  // self_norm
        float4 h = accs[i];
        *(float4*)&g_h[gn * HID + c0] = h;
        float4 ag;
        ag.x = h.x * sn + bb.x;
        ag.y = h.y * sn + bb.y;
        ag.z = h.z * sn + bb.z;
        ag.w = h.w * sn + bb.w;
        *(float4*)&g_agg[gn * HID + c0] = ag;
    }
}

// ---------------- edge scatter: agg[dst] += h[src] * enorm ----------------
__global__ __launch_bounds__(256) void scatter_kernel(const int* __restrict__ src,
                                                      const int* __restrict__ dst) {
    __shared__ int   s_s[256];
    __shared__ int   s_d[256];
    __shared__ float s_e[256];
    int tid  = threadIdx.x;
    int base = blockIdx.x * 256;
    int cnt  = min(256, N_EDGES - base);
    if (tid < cnt) {
        s_s[tid] = src[base + tid];
        s_d[tid] = dst[base + tid];
        s_e[tid] = g_enorm[base + tid];
    }
    __syncthreads();

    int c4 = (tid & 15) * 4;
    for (int i = tid >> 4; i < cnt; i += 16) {
        int s = s_s[i];
        int d = s_d[i];
        float en = s_e[i];
        float4 v = *(const float4*)&g_h[s * HID + c4];
        v.x *= en; v.y *= en; v.z *= en; v.w *= en;
        asm volatile("red.global.add.v4.f32 [%0], {%1,%2,%3,%4};"
                     :: "l"(&g_agg[d * HID + c4]),
                        "f"(v.x), "f"(v.y), "f"(v.z), "f"(v.w)
                     : "memory");
    }
}

// ---------------- relu (in place) + per-channel sum/sumsq ----------------
__global__ __launch_bounds__(256) void relu_stats_kernel() {
    int tid = threadIdx.x;
    int c = tid & 63, r = tid >> 6;
    int base = blockIdx.x * 256;
    int lim = min(base + 256, N_NODES);
    float s = 0.f, sq = 0.f;
    for (int n = base + r; n < lim; n += 4) {
        int idx = n * HID + c;
        float v = g_agg[idx];
        v = fmaxf(v, 0.f);
        g_agg[idx] = v;
        s += v;
        sq += v * v;
    }
    __shared__ float sm[512];
    sm[tid] = s;
    sm[256 + tid] = sq;
    __syncthreads();
    if (r == 0) {
        s  = sm[c] + sm[c + 64] + sm[c + 128] + sm[c + 192];
        sq = sm[256 + c] + sm[256 + c + 64] + sm[256 + c + 128] + sm[256 + c + 192];
        atomicAdd(&g_stats[c], s);
        atomicAdd(&g_stats[HID + c], sq);
    }
}

// ---------------- BN affine coefficients ----------------
__global__ void affine_kernel(const float* __restrict__ g, const float* __restrict__ be) {
    int c = threadIdx.x;
    if (c < HID) {
        float mean = g_stats[c] * (1.f / N_NODES);
        float var  = g_stats[HID + c] * (1.f / N_NODES) - mean * mean;
        float a = g[c] * rsqrtf(var + BN_EPS);
        g_affine[c] = a;
        g_affine[HID + c] = be[c] - mean * a;
    }
}

// ---------------- global add pool (applies final BN affine) ----------------
__global__ __launch_bounds__(256) void pool_kernel(const int* __restrict__ batch,
                                                   float* __restrict__ out) {
    __shared__ int s_bt[256];
    int tid  = threadIdx.x;
    int base = blockIdx.x * 256;
    int cnt  = min(256, N_NODES - base);
    if (tid < cnt) s_bt[tid] = batch[base + tid];
    __syncthreads();

    int c4 = (tid & 15) * 4;
    float4 a4 = *(const float4*)&g_affine[c4];
    float4 d4 = *(const float4*)&g_affine[HID + c4];
    for (int i = tid >> 4; i < cnt; i += 16) {
        int n = base + i;
        float4 v = *(const float4*)&g_agg[n * HID + c4];
        float4 r;
        r.x = v.x * a4.x + d4.x;
        r.y = v.y * a4.y + d4.y;
        r.z = v.z * a4.z + d4.z;
        r.w = v.w * a4.w + d4.w;
        asm volatile("red.global.add.v4.f32 [%0], {%1,%2,%3,%4};"
                     :: "l"(&out[s_bt[i] * HID + c4]),
                        "f"(r.x), "f"(r.y), "f"(r.z), "f"(r.w)
                     : "memory");
    }
}

// ---------------- launch ----------------
extern "C" void kernel_launch(void* const* d_in, const int* in_sizes, int n_in,
                              void* d_out, int out_size) {
    const float* x     = (const float*)d_in[0];
    const int*   src   = (const int*)d_in[1];
    const int*   dst   = (const int*)d_in[2];
    const int*   batch = (const int*)d_in[3];
    const float* W[4];
    const float* b[4];
    const float* g[4];
    const float* be[4];
    for (int i = 0; i < 4; i++) {
        W[i]  = (const float*)d_in[4 + 4 * i];
        b[i]  = (const float*)d_in[5 + 4 * i];
        g[i]  = (const float*)d_in[6 + 4 * i];
        be[i] = (const float*)d_in[7 + 4 * i];
    }
    float* out = (float*)d_out;

    const int NB_NODES = (N_NODES + 255) / 256;   // 391
    const int NB_EDGES = (N_EDGES + 255) / 256;   // 6250
    const int NB_GEMM  = (N_NODES + 63) / 64;     // 1563

    cudaMemsetAsync(d_out, 0, (size_t)out_size * sizeof(float), 0);

    zero_deg_kernel<<<NB_NODES, 256>>>();
    deg_kernel<<<NB_EDGES, 256>>>(dst);
    dinv_kernel<<<NB_NODES, 256>>>();
    enorm_kernel<<<NB_EDGES, 256>>>(src, dst);

    // layer 1 (input: x, 75 features)
    gemm_kernel<75, false><<<NB_GEMM, 256>>>(x, W[0], b[0]);
    scatter_kernel<<<NB_EDGES, 256>>>(src, dst);
    relu_stats_kernel<<<NB_NODES, 256>>>();
    affine_kernel<<<1, 64>>>(g[0], be[0]);

    // layers 2..4 (input: g_agg with folded BN affine)
    for (int l = 1; l < 4; l++) {
        gemm_kernel<64, true><<<NB_GEMM, 256>>>(nullptr, W[l], b[l]);
        scatter_kernel<<<NB_EDGES, 256>>>(src, dst);
        relu_stats_kernel<<<NB_NODES, 256>>>();
        affine_kernel<<<1, 64>>>(g[l], be[l]);
    }

    pool_kernel<<<NB_NODES, 256>>>(batch, out);
}

// round 3
// speedup vs baseline: 1.2029x; 1.2029x over previous
#include <cuda_runtime.h>

#define N_NODES 100000
#define N_EDGES 1600000
#define HID 64
#define NGRAPH 4096
#define BN_EPS 1e-5f
#define SCAN_B 1024
#define SCAN_NB ((N_NODES + SCAN_B - 1) / SCAN_B)   // 98

// ---------------- scratch (device globals; no allocations) ----------------
__device__ __align__(16) float g_h[N_NODES * HID];    // linear output h (gather source)
__device__ __align__(16) float g_y[N_NODES * HID];    // post-relu layer output
__device__ int   g_cnt[N_NODES];                      // in-degree (histogram)
__device__ float g_dinv[N_NODES];
__device__ int   g_rowptr[N_NODES];
__device__ int   g_cursor[N_NODES];
__device__ int   g_eidx[N_EDGES];                     // src idx sorted by dst
__device__ int   g_blksum[SCAN_NB];
__device__ float g_stats[2 * HID];                    // [sum(64), sumsq(64)]
__device__ __align__(16) float g_affine[2 * HID];     // [a(64), d(64)]: x' = y*a + d

// ---------------- CSR build ----------------
__global__ void zero_cnt_kernel() {
    int i = blockIdx.x * blockDim.x + threadIdx.x;
    if (i < N_NODES) g_cnt[i] = 0;
}

__global__ void hist_kernel(const int* __restrict__ dst) {
    int e = blockIdx.x * blockDim.x + threadIdx.x;
    if (e < N_EDGES) atomicAdd(&g_cnt[dst[e]], 1);
}

__global__ void dinv_kernel() {
    int i = blockIdx.x * blockDim.x + threadIdx.x;
    if (i < N_NODES) g_dinv[i] = rsqrtf((float)g_cnt[i] + 1.f);
}

__global__ __launch_bounds__(SCAN_B) void scan1_kernel() {
    __shared__ int sm[SCAN_B];
    int t = threadIdx.x;
    int i = blockIdx.x * SCAN_B + t;
    int v = (i < N_NODES) ? g_cnt[i] : 0;
    sm[t] = v;
    __syncthreads();
    for (int off = 1; off < SCAN_B; off <<= 1) {
        int x = (t >= off) ? sm[t - off] : 0;
        __syncthreads();
        sm[t] += x;
        __syncthreads();
    }
    if (i < N_NODES) g_rowptr[i] = sm[t] - v;  // exclusive (block-local)
    if (t == SCAN_B - 1) g_blksum[blockIdx.x] = sm[t];
}

__global__ void scan2_kernel() {
    int run = 0;
    for (int b = 0; b < SCAN_NB; b++) {
        int t = g_blksum[b];
        g_blksum[b] = run;
        run += t;
    }
}

__global__ __launch_bounds__(SCAN_B) void scan3_kernel() {
    int i = blockIdx.x * SCAN_B + threadIdx.x;
    if (i < N_NODES) {
        int r = g_rowptr[i] + g_blksum[blockIdx.x];
        g_rowptr[i] = r;
        g_cursor[i] = r;
    }
}

__global__ void fill_kernel(const int* __restrict__ src, const int* __restrict__ dst) {
    int e = blockIdx.x * blockDim.x + threadIdx.x;
    if (e < N_EDGES) {
        int d = dst[e];
        int pos = atomicAdd(&g_cursor[d], 1);
        g_eidx[pos] = src[e];
    }
}

// ---------------- GEMM: h = X @ W ----------------
// Block: 256 threads, 64-node tile, each thread computes 4 nodes x 4 cols.
// FROM_Y: read input from g_y (previous layer's post-relu y) and apply
// the folded BN affine x' = y*a[k] + d[k].
template <int IN, bool FROM_Y>
__global__ __launch_bounds__(256) void gemm_kernel(const float* __restrict__ X,
                                                   const float* __restrict__ W) {
    __shared__ __align__(16) float Ws[IN * HID];
    __shared__ float Xs[64 * (IN + 1)];
    __shared__ float s_a[HID];
    __shared__ float s_dd[HID];

    int tid = threadIdx.x;

    // zero BN stats for this layer (prev affine already consumed them)
    if (blockIdx.x == 0 && tid < 2 * HID) g_stats[tid] = 0.f;

    for (int i = tid; i < IN * HID; i += 256) Ws[i] = W[i];
    if (FROM_Y && tid < HID) {
        s_a[tid]  = g_affine[tid];
        s_dd[tid] = g_affine[HID + tid];
    }
    __syncthreads();

    int base = blockIdx.x * 64;
    for (int i = tid; i < 64 * IN; i += 256) {
        int n = i / IN, k = i - n * IN;
        int gn = base + n;
        float v = 0.f;
        if (gn < N_NODES) {
            if (FROM_Y) v = g_y[gn * HID + k] * s_a[k] + s_dd[k];
            else        v = X[gn * IN + k];
        }
        Xs[n * (IN + 1) + k] = v;
    }
    __syncthreads();

    int tx = tid & 15, ty = tid >> 4;
    int c0 = tx * 4, n0 = ty * 4;
    float4 a0 = {0.f, 0.f, 0.f, 0.f};
    float4 a1 = {0.f, 0.f, 0.f, 0.f};
    float4 a2 = {0.f, 0.f, 0.f, 0.f};
    float4 a3 = {0.f, 0.f, 0.f, 0.f};

#pragma unroll 5
    for (int k = 0; k < IN; k++) {
        float4 w = *(const float4*)&Ws[k * HID + c0];
        float x0 = Xs[(n0 + 0) * (IN + 1) + k];
        float x1 = Xs[(n0 + 1) * (IN + 1) + k];
        float x2 = Xs[(n0 + 2) * (IN + 1) + k];
        float x3 = Xs[(n0 + 3) * (IN + 1) + k];
        a0.x += x0 * w.x; a0.y += x0 * w.y; a0.z += x0 * w.z; a0.w += x0 * w.w;
        a1.x += x1 * w.x; a1.y += x1 * w.y; a1.z += x1 * w.z; a1.w += x1 * w.w;
        a2.x += x2 * w.x; a2.y += x2 * w.y; a2.z += x2 * w.z; a2.w += x2 * w.w;
        a3.x += x3 * w.x; a3.y += x3 * w.y; a3.z += x3 * w.z; a3.w += x3 * w.w;
    }

    float4 accs[4] = {a0, a1, a2, a3};
#pragma unroll
    for (int i = 0; i < 4; i++) {
        int gn = base + n0 + i;
        if (gn >= N_NODES) break;
        *(float4*)&g_h[gn * HID + c0] = accs[i];
    }
}

// ---------------- gather aggregation + relu + BN stats ----------------
// 256 threads = 16 groups of 16 lanes; each group owns one dst node.
// grid = N_NODES/16 = 6250 blocks (exact).
// NOTE: shuffles use half-warp masks + width=16 so the two 16-lane groups
// sharing a warp may diverge in loop trip count without UB.
__global__ __launch_bounds__(256) void gather_kernel(const float* __restrict__ bias) {
    __shared__ float s_b[HID];
    __shared__ float sm_s[16][HID + 4];
    __shared__ float sm_q[16][HID + 4];

    int tid   = threadIdx.x;
    int grp   = tid >> 4;
    int lane  = tid & 15;
    unsigned hmask = 0xFFFFu << ((tid & 31) & 16);  // this half-warp's lanes
    int c4    = lane * 4;

    if (tid < HID) s_b[tid] = bias[tid];
    __syncthreads();

    int n = blockIdx.x * 16 + grp;
    float dv = g_dinv[n];
    float sn = dv * dv;

    float4 acc = *(const float4*)&g_h[n * HID + c4];
    float4 bb  = *(const float4*)&s_b[c4];
    acc.x = acc.x * sn + bb.x;
    acc.y = acc.y * sn + bb.y;
    acc.z = acc.z * sn + bb.z;
    acc.w = acc.w * sn + bb.w;

    int start = g_rowptr[n];
    int len   = g_cnt[n];

    for (int j0 = 0; j0 < len; j0 += 16) {
        int myj = j0 + lane;
        int sidx = 0;
        float w = 0.f;
        if (myj < len) {
            sidx = g_eidx[start + myj];
            w = dv * g_dinv[sidx];
        }
        int m = min(16, len - j0);
        for (int j = 0; j < m; j++) {
            int   s  = __shfl_sync(hmask, sidx, j, 16);
            float wj = __shfl_sync(hmask, w,    j, 16);
            float4 hv = *(const float4*)&g_h[s * HID + c4];
            acc.x += hv.x * wj;
            acc.y += hv.y * wj;
            acc.z += hv.z * wj;
            acc.w += hv.w * wj;
        }
    }

    // relu + store
    acc.x = fmaxf(acc.x, 0.f);
    acc.y = fmaxf(acc.y, 0.f);
    acc.z = fmaxf(acc.z, 0.f);
    acc.w = fmaxf(acc.w, 0.f);
    *(float4*)&g_y[n * HID + c4] = acc;

    // BN stats: per-group row, then reduce over 16 groups
    sm_s[grp][c4 + 0] = acc.x; sm_q[grp][c4 + 0] = acc.x * acc.x;
    sm_s[grp][c4 + 1] = acc.y; sm_q[grp][c4 + 1] = acc.y * acc.y;
    sm_s[grp][c4 + 2] = acc.z; sm_q[grp][c4 + 2] = acc.z * acc.z;
    sm_s[grp][c4 + 3] = acc.w; sm_q[grp][c4 + 3] = acc.w * acc.w;
    __syncthreads();
    if (tid < HID) {
        float s = 0.f, q = 0.f;
#pragma unroll
        for (int r = 0; r < 16; r++) {
            s += sm_s[r][tid];
            q += sm_q[r][tid];
        }
        asm volatile("red.global.add.f32 [%0], %1;" :: "l"(&g_stats[tid]), "f"(s) : "memory");
        asm volatile("red.global.add.f32 [%0], %1;" :: "l"(&g_stats[HID + tid]), "f"(q) : "memory");
    }
}

// ---------------- BN affine coefficients ----------------
__global__ void affine_kernel(const float* __restrict__ g, const float* __restrict__ be) {
    int c = threadIdx.x;
    if (c < HID) {
        float mean = g_stats[c] * (1.f / N_NODES);
        float var  = g_stats[HID + c] * (1.f / N_NODES) - mean * mean;
        float a = g[c] * rsqrtf(var + BN_EPS);
        g_affine[c] = a;
        g_affine[HID + c] = be[c] - mean * a;
    }
}

// ---------------- global add pool (applies final BN affine) ----------------
__global__ __launch_bounds__(256) void pool_kernel(const int* __restrict__ batch,
                                                   float* __restrict__ out) {
    __shared__ int s_bt[256];
    int tid  = threadIdx.x;
    int base = blockIdx.x * 256;
    int cnt  = min(256, N_NODES - base);
    if (tid < cnt) s_bt[tid] = batch[base + tid];
    __syncthreads();

    int c4 = (tid & 15) * 4;
    float4 a4 = *(const float4*)&g_affine[c4];
    float4 d4 = *(const float4*)&g_affine[HID + c4];
    for (int i = tid >> 4; i < cnt; i += 16) {
        int n = base + i;
        float4 v = *(const float4*)&g_y[n * HID + c4];
        float4 r;
        r.x = v.x * a4.x + d4.x;
        r.y = v.y * a4.y + d4.y;
        r.z = v.z * a4.z + d4.z;
        r.w = v.w * a4.w + d4.w;
        asm volatile("red.global.add.v4.f32 [%0], {%1,%2,%3,%4};"
                     :: "l"(&out[s_bt[i] * HID + c4]),
                        "f"(r.x), "f"(r.y), "f"(r.z), "f"(r.w)
                     : "memory");
    }
}

// ---------------- launch ----------------
extern "C" void kernel_launch(void* const* d_in, const int* in_sizes, int n_in,
                              void* d_out, int out_size) {
    const float* x     = (const float*)d_in[0];
    const int*   src   = (const int*)d_in[1];
    const int*   dst   = (const int*)d_in[2];
    const int*   batch = (const int*)d_in[3];
    const float* W[4];
    const float* b[4];
    const float* g[4];
    const float* be[4];
    for (int i = 0; i < 4; i++) {
        W[i]  = (const float*)d_in[4 + 4 * i];
        b[i]  = (const float*)d_in[5 + 4 * i];
        g[i]  = (const float*)d_in[6 + 4 * i];
        be[i] = (const float*)d_in[7 + 4 * i];
    }
    float* out = (float*)d_out;

    const int NB_NODES = (N_NODES + 255) / 256;   // 391
    const int NB_EDGES = (N_EDGES + 255) / 256;   // 6250
    const int NB_GEMM  = (N_NODES + 63) / 64;     // 1563
    const int NB_GATH  = N_NODES / 16;            // 6250 (exact)

    cudaMemsetAsync(d_out, 0, (size_t)out_size * sizeof(float), 0);

    // CSR build + norms
    zero_cnt_kernel<<<NB_NODES, 256>>>();
    hist_kernel<<<NB_EDGES, 256>>>(dst);
    dinv_kernel<<<NB_NODES, 256>>>();
    scan1_kernel<<<SCAN_NB, SCAN_B>>>();
    scan2_kernel<<<1, 1>>>();
    scan3_kernel<<<SCAN_NB, SCAN_B>>>();
    fill_kernel<<<NB_EDGES, 256>>>(src, dst);

    // layer 1 (input: x, 75 features)
    gemm_kernel<75, false><<<NB_GEMM, 256>>>(x, W[0]);
    gather_kernel<<<NB_GATH, 256>>>(b[0]);
    affine_kernel<<<1, 64>>>(g[0], be[0]);

    // layers 2..4 (input: g_y with folded BN affine)
    for (int l = 1; l < 4; l++) {
        gemm_kernel<64, true><<<NB_GEMM, 256>>>(nullptr, W[l]);
        gather_kernel<<<NB_GATH, 256>>>(b[l]);
        affine_kernel<<<1, 64>>>(g[l], be[l]);
    }

    pool_kernel<<<NB_NODES, 256>>>(batch, out);
}

// round 4
// speedup vs baseline: 1.2917x; 1.0738x over previous
#include <cuda_runtime.h>

#define N_NODES 100000
#define N_EDGES 1600000
#define HID 64
#define NGRAPH 4096
#define BN_EPS 1e-5f
#define SCAN_B 1024
#define SCAN_NB ((N_NODES + SCAN_B - 1) / SCAN_B)   // 98
#define N_TILES (N_NODES / 16)                      // 6250 (exact)
#define GATH_GRID 1184

// ---------------- scratch (device globals; no allocations) ----------------
__device__ __align__(16) float g_h[N_NODES * HID];    // linear output h (gather source)
__device__ __align__(16) float g_y[N_NODES * HID];    // post-relu layer output
__device__ int   g_cnt[N_NODES];                      // in-degree (histogram)
__device__ float g_dinv[N_NODES];
__device__ int   g_rowptr[N_NODES];
__device__ int   g_cursor[N_NODES];
__device__ int   g_eidx[N_EDGES];                     // src idx sorted by dst
__device__ int   g_blksum[SCAN_NB];
__device__ float g_stats[2][2 * HID];                 // ping-pong [sum(64), sumsq(64)]

// ---------------- CSR build ----------------
__global__ void hist_kernel(const int* __restrict__ dst) {
    int e = blockIdx.x * blockDim.x + threadIdx.x;
    if (e < N_EDGES) atomicAdd(&g_cnt[dst[e]], 1);
}

__global__ __launch_bounds__(SCAN_B) void scan1_kernel() {
    __shared__ int sm[SCAN_B];
    int t = threadIdx.x;
    int i = blockIdx.x * SCAN_B + t;
    int v = (i < N_NODES) ? g_cnt[i] : 0;
    sm[t] = v;
    __syncthreads();
    for (int off = 1; off < SCAN_B; off <<= 1) {
        int x = (t >= off) ? sm[t - off] : 0;
        __syncthreads();
        sm[t] += x;
        __syncthreads();
    }
    if (i < N_NODES) g_rowptr[i] = sm[t] - v;  // exclusive (block-local)
    if (t == SCAN_B - 1) g_blksum[blockIdx.x] = sm[t];
}

__global__ void scan2_kernel() {
    int run = 0;
    for (int b = 0; b < SCAN_NB; b++) {
        int t = g_blksum[b];
        g_blksum[b] = run;
        run += t;
    }
}

// scan finalize + cursor init + dinv (folded)
__global__ __launch_bounds__(SCAN_B) void scan3_kernel() {
    int i = blockIdx.x * SCAN_B + threadIdx.x;
    if (i < N_NODES) {
        int r = g_rowptr[i] + g_blksum[blockIdx.x];
        g_rowptr[i] = r;
        g_cursor[i] = r;
        g_dinv[i] = rsqrtf((float)g_cnt[i] + 1.f);
    }
}

__global__ void fill_kernel(const int* __restrict__ src, const int* __restrict__ dst) {
    int e = blockIdx.x * blockDim.x + threadIdx.x;
    if (e < N_EDGES) {
        int d = dst[e];
        int pos = atomicAdd(&g_cursor[d], 1);
        g_eidx[pos] = src[e];
    }
}

// ---------------- GEMM: h = X @ W ----------------
// Block: 256 threads, 64-node tile, each thread computes 4 nodes x 4 cols.
// FROM_Y: input = g_y with folded BN affine (computed inline from g_stats[rdp]).
// Every block also zeroes g_stats[wrp] (same value, benign race) for the
// gather that follows this GEMM.
template <int IN, bool FROM_Y>
__global__ __launch_bounds__(256) void gemm_kernel(const float* __restrict__ X,
                                                   const float* __restrict__ W,
                                                   const float* __restrict__ gam,
                                                   const float* __restrict__ bet,
                                                   int rdp, int wrp) {
    __shared__ __align__(16) float Ws[IN * HID];
    __shared__ float Xs[64 * (IN + 1)];
    __shared__ float s_a[HID];
    __shared__ float s_dd[HID];

    int tid = threadIdx.x;

    if (tid < 2 * HID) g_stats[wrp][tid] = 0.f;

    for (int i = tid; i < IN * HID; i += 256) Ws[i] = W[i];
    if (FROM_Y && tid < HID) {
        float mean = g_stats[rdp][tid] * (1.f / N_NODES);
        float var  = g_stats[rdp][HID + tid] * (1.f / N_NODES) - mean * mean;
        float a = gam[tid] * rsqrtf(var + BN_EPS);
        s_a[tid]  = a;
        s_dd[tid] = bet[tid] - mean * a;
    }
    __syncthreads();

    int base = blockIdx.x * 64;
    for (int i = tid; i < 64 * IN; i += 256) {
        int n = i / IN, k = i - n * IN;
        int gn = base + n;
        float v = 0.f;
        if (gn < N_NODES) {
            if (FROM_Y) v = g_y[gn * HID + k] * s_a[k] + s_dd[k];
            else        v = X[gn * IN + k];
        }
        Xs[n * (IN + 1) + k] = v;
    }
    __syncthreads();

    int tx = tid & 15, ty = tid >> 4;
    int c0 = tx * 4, n0 = ty * 4;
    float4 a0 = {0.f, 0.f, 0.f, 0.f};
    float4 a1 = {0.f, 0.f, 0.f, 0.f};
    float4 a2 = {0.f, 0.f, 0.f, 0.f};
    float4 a3 = {0.f, 0.f, 0.f, 0.f};

#pragma unroll 5
    for (int k = 0; k < IN; k++) {
        float4 w = *(const float4*)&Ws[k * HID + c0];
        float x0 = Xs[(n0 + 0) * (IN + 1) + k];
        float x1 = Xs[(n0 + 1) * (IN + 1) + k];
        float x2 = Xs[(n0 + 2) * (IN + 1) + k];
        float x3 = Xs[(n0 + 3) * (IN + 1) + k];
        a0.x += x0 * w.x; a0.y += x0 * w.y; a0.z += x0 * w.z; a0.w += x0 * w.w;
        a1.x += x1 * w.x; a1.y += x1 * w.y; a1.z += x1 * w.z; a1.w += x1 * w.w;
        a2.x += x2 * w.x; a2.y += x2 * w.y; a2.z += x2 * w.z; a2.w += x2 * w.w;
        a3.x += x3 * w.x; a3.y += x3 * w.y; a3.z += x3 * w.z; a3.w += x3 * w.w;
    }

    float4 accs[4] = {a0, a1, a2, a3};
#pragma unroll
    for (int i = 0; i < 4; i++) {
        int gn = base + n0 + i;
        if (gn >= N_NODES) break;
        *(float4*)&g_h[gn * HID + c0] = accs[i];
    }
}

// ---------------- gather aggregation + relu + BN stats ----------------
// Persistent grid-stride: 16 groups of 16 lanes per block, one node per group
// per tile. BN stats accumulate in registers across tiles; single smem
// reduction + 128 global reds per block at the end.
__global__ __launch_bounds__(256) void gather_kernel(const float* __restrict__ bias,
                                                     int wrp) {
    __shared__ float s_b[HID];
    __shared__ float sm_s[16][HID + 4];
    __shared__ float sm_q[16][HID + 4];

    int tid   = threadIdx.x;
    int grp   = tid >> 4;
    int lane  = tid & 15;
    unsigned hmask = 0xFFFFu << ((tid & 31) & 16);  // this half-warp's lanes
    int c4    = lane * 4;

    if (tid < HID) s_b[tid] = bias[tid];
    __syncthreads();
    float4 bb = *(const float4*)&s_b[c4];

    float4 s4 = {0.f, 0.f, 0.f, 0.f};
    float4 q4 = {0.f, 0.f, 0.f, 0.f};

    for (int tile = blockIdx.x; tile < N_TILES; tile += GATH_GRID) {
        int n = tile * 16 + grp;
        float dv = g_dinv[n];
        float sn = dv * dv;

        float4 acc = *(const float4*)&g_h[n * HID + c4];
        acc.x = acc.x * sn + bb.x;
        acc.y = acc.y * sn + bb.y;
        acc.z = acc.z * sn + bb.z;
        acc.w = acc.w * sn + bb.w;

        int start = g_rowptr[n];
        int len   = g_cnt[n];

        for (int j0 = 0; j0 < len; j0 += 16) {
            int myj = j0 + lane;
            int sidx = 0;
            float w = 0.f;
            if (myj < len) {
                sidx = g_eidx[start + myj];
                w = dv * g_dinv[sidx];
            }
#pragma unroll
            for (int j = 0; j < 16; j++) {
                int   s  = __shfl_sync(hmask, sidx, j, 16);
                float wj = __shfl_sync(hmask, w,    j, 16);
                float4 hv = *(const float4*)&g_h[s * HID + c4];
                acc.x += hv.x * wj;
                acc.y += hv.y * wj;
                acc.z += hv.z * wj;
                acc.w += hv.w * wj;
            }
        }

        acc.x = fmaxf(acc.x, 0.f);
        acc.y = fmaxf(acc.y, 0.f);
        acc.z = fmaxf(acc.z, 0.f);
        acc.w = fmaxf(acc.w, 0.f);
        *(float4*)&g_y[n * HID + c4] = acc;

        s4.x += acc.x; q4.x += acc.x * acc.x;
        s4.y += acc.y; q4.y += acc.y * acc.y;
        s4.z += acc.z; q4.z += acc.z * acc.z;
        s4.w += acc.w; q4.w += acc.w * acc.w;
    }

    sm_s[grp][c4 + 0] = s4.x; sm_q[grp][c4 + 0] = q4.x;
    sm_s[grp][c4 + 1] = s4.y; sm_q[grp][c4 + 1] = q4.y;
    sm_s[grp][c4 + 2] = s4.z; sm_q[grp][c4 + 2] = q4.z;
    sm_s[grp][c4 + 3] = s4.w; sm_q[grp][c4 + 3] = q4.w;
    __syncthreads();
    if (tid < HID) {
        float s = 0.f, q = 0.f;
#pragma unroll
        for (int r = 0; r < 16; r++) {
            s += sm_s[r][tid];
            q += sm_q[r][tid];
        }
        asm volatile("red.global.add.f32 [%0], %1;" :: "l"(&g_stats[wrp][tid]), "f"(s) : "memory");
        asm volatile("red.global.add.f32 [%0], %1;" :: "l"(&g_stats[wrp][HID + tid]), "f"(q) : "memory");
    }
}

// ---------------- global add pool (applies final BN affine) ----------------
// batch is sorted: each 16-lane group walks 16 consecutive nodes and flushes
// one red.v4 per graph-id change.
__global__ __launch_bounds__(256) void pool_kernel(const int* __restrict__ batch,
                                                   float* __restrict__ out,
                                                   const float* __restrict__ gam,
                                                   const float* __restrict__ bet) {
    __shared__ float s_a[HID];
    __shared__ float s_d[HID];
    int tid = threadIdx.x;
    if (tid < HID) {
        float mean = g_stats[1][tid] * (1.f / N_NODES);
        float var  = g_stats[1][HID + tid] * (1.f / N_NODES) - mean * mean;
        float a = gam[tid] * rsqrtf(var + BN_EPS);
        s_a[tid] = a;
        s_d[tid] = bet[tid] - mean * a;
    }
    __syncthreads();

    int grp = tid >> 4, lane = tid & 15;
    int c4 = lane * 4;
    float4 a4 = *(const float4*)&s_a[c4];
    float4 d4 = *(const float4*)&s_d[c4];

    int base = blockIdx.x * 256 + grp * 16;
    float4 run = {0.f, 0.f, 0.f, 0.f};
    int cur = -1;
    for (int i = 0; i < 16; i++) {
        int n = base + i;
        if (n >= N_NODES) break;
        int bt = batch[n];
        if (bt != cur) {
            if (cur >= 0) {
                asm volatile("red.global.add.v4.f32 [%0], {%1,%2,%3,%4};"
                             :: "l"(&out[cur * HID + c4]),
                                "f"(run.x), "f"(run.y), "f"(run.z), "f"(run.w) : "memory");
            }
            run.x = run.y = run.z = run.w = 0.f;
            cur = bt;
        }
        float4 v = *(const float4*)&g_y[n * HID + c4];
        run.x += v.x * a4.x + d4.x;
        run.y += v.y * a4.y + d4.y;
        run.z += v.z * a4.z + d4.z;
        run.w += v.w * a4.w + d4.w;
    }
    if (cur >= 0) {
        asm volatile("red.global.add.v4.f32 [%0], {%1,%2,%3,%4};"
                     :: "l"(&out[cur * HID + c4]),
                        "f"(run.x), "f"(run.y), "f"(run.z), "f"(run.w) : "memory");
    }
}

// ---------------- launch ----------------
extern "C" void kernel_launch(void* const* d_in, const int* in_sizes, int n_in,
                              void* d_out, int out_size) {
    const float* x     = (const float*)d_in[0];
    const int*   src   = (const int*)d_in[1];
    const int*   dst   = (const int*)d_in[2];
    const int*   batch = (const int*)d_in[3];
    const float* W[4];
    const float* b[4];
    const float* g[4];
    const float* be[4];
    for (int i = 0; i < 4; i++) {
        W[i]  = (const float*)d_in[4 + 4 * i];
        b[i]  = (const float*)d_in[5 + 4 * i];
        g[i]  = (const float*)d_in[6 + 4 * i];
        be[i] = (const float*)d_in[7 + 4 * i];
    }
    float* out = (float*)d_out;

    const int NB_NODES = (N_NODES + 255) / 256;   // 391
    const int NB_EDGES = (N_EDGES + 255) / 256;   // 6250
    const int NB_GEMM  = (N_NODES + 63) / 64;     // 1563

    cudaMemsetAsync(d_out, 0, (size_t)out_size * sizeof(float), 0);
    void* p_cnt = nullptr;
    cudaGetSymbolAddress(&p_cnt, g_cnt);
    cudaMemsetAsync(p_cnt, 0, N_NODES * sizeof(int), 0);

    // CSR build + norms
    hist_kernel<<<NB_EDGES, 256>>>(dst);
    scan1_kernel<<<SCAN_NB, SCAN_B>>>();
    scan2_kernel<<<1, 1>>>();
    scan3_kernel<<<SCAN_NB, SCAN_B>>>();
    fill_kernel<<<NB_EDGES, 256>>>(src, dst);

    // layer 1 (input: x, 75 features); stats parity: gather_l writes stats[l&1]
    gemm_kernel<75, false><<<NB_GEMM, 256>>>(x, W[0], nullptr, nullptr, 0, 0);
    gather_kernel<<<GATH_GRID, 256>>>(b[0], 0);

    // layers 2..4
    for (int l = 1; l < 4; l++) {
        gemm_kernel<64, true><<<NB_GEMM, 256>>>(nullptr, W[l], g[l - 1], be[l - 1],
                                                (l - 1) & 1, l & 1);
        gather_kernel<<<GATH_GRID, 256>>>(b[l], l & 1);
    }

    pool_kernel<<<NB_NODES, 256>>>(batch, out, g[3], be[3]);
}